// round 1
// baseline (speedup 1.0000x reference)
#include <cuda_runtime.h>

#define XH 130
#define XW 130
#define XC 64
#define NRED 16
#define NSPAN 196
#define NLAYERS 6
#define TILE 8
#define TS 14          // TILE + 6 halo
#define NTB 17         // ceil(130/8)

// ---------------- scratch (device globals; no allocation) ----------------
__device__ float g_bufA[XH * XW * XC];
__device__ float g_bufB[XH * XW * XC];
__device__ float g_redT[NLAYERS][XC * NRED];     // gamma-folded, [c][r]
__device__ float g_spanT[NLAYERS][NRED * NSPAN]; // [r][j]

// ---------------- prep: transpose 1x1 weights, fold BN gamma ----------------
__global__ void prep_kernel(const float* __restrict__ red_w,
                            const float* __restrict__ gamma,
                            const float* __restrict__ span_w) {
    int idx = blockIdx.x * blockDim.x + threadIdx.x;
    if (idx < NLAYERS * XC * NRED) {
        int l = idx / (XC * NRED), rem = idx % (XC * NRED);
        int c = rem / NRED, r = rem % NRED;
        g_redT[l][c * NRED + r] = gamma[l * NRED + r] * red_w[(l * NRED + r) * XC + c];
    }
    int idx2 = idx - NLAYERS * XC * NRED;
    if (idx2 >= 0 && idx2 < NLAYERS * NRED * NSPAN) {
        int l = idx2 / (NRED * NSPAN), rem = idx2 % (NRED * NSPAN);
        int r = rem / NSPAN, j = rem % NSPAN;
        g_spanT[l][r * NSPAN + j] = span_w[(l * NSPAN + j) * NRED + r];
    }
}

// ---------------- conv_in: 3->64, 3x3, pad 2 ; NCHW in -> NHWC out ----------------
__global__ void conv_in_kernel(const float* __restrict__ in,
                               const float* __restrict__ w,
                               const float* __restrict__ b,
                               float* __restrict__ out) {
    __shared__ float ws[27 * 64];
    int tid = threadIdx.x;
    for (int i = tid; i < 27 * 64; i += blockDim.x) {
        int t = i >> 6, c = i & 63;
        ws[t * 64 + c] = w[c * 27 + t];
    }
    __syncthreads();
    int idx = blockIdx.x * blockDim.x + tid;   // pixel*64 + c
    if (idx >= XH * XW * XC) return;
    int c = idx & 63;
    int p = idx >> 6;
    int y = p / XW, x = p % XW;
    float acc = b[c];
#pragma unroll
    for (int i = 0; i < 3; i++)
#pragma unroll
        for (int ky = 0; ky < 3; ky++) {
            int yy = y + ky - 2;
            if (yy < 0 || yy >= 128) continue;
#pragma unroll
            for (int kx = 0; kx < 3; kx++) {
                int xx = x + kx - 2;
                if (xx < 0 || xx >= 128) continue;
                acc = fmaf(ws[(i * 9 + ky * 3 + kx) * 64 + c],
                           in[(i * 128 + yy) * 128 + xx], acc);
            }
        }
    out[p * 64 + c] = acc;
}

// ---------------- involution block (one layer), NHWC ----------------
__global__ void __launch_bounds__(128)
involution_kernel(const float* __restrict__ xin, float* __restrict__ xout,
                  const float* __restrict__ redT, const float* __restrict__ spanT,
                  const float* __restrict__ beta, const float* __restrict__ span_b) {
    extern __shared__ float sm[];
    float* xs      = sm;                      // TS*TS*64 = 12544
    float* redT_s  = xs + TS * TS * XC;       // 1024
    float* spanT_s = redT_s + XC * NRED;      // 3136
    float* sb_s    = spanT_s + NRED * NSPAN;  // 196
    float* beta_s  = sb_s + NSPAN;            // 16
    float* t_s     = beta_s + 16;             // 4*16
    float* ker_s   = t_s + 64;                // 4*200

    int tid = threadIdx.x;
    int lane = tid & 31, warp = tid >> 5;
    int by = blockIdx.x / NTB, bx = blockIdx.x % NTB;
    int y0 = by * TILE - 3, x0 = bx * TILE - 3;

    // stage weights (coalesced, pre-transposed)
    for (int i = tid; i < XC * NRED; i += 128) redT_s[i] = redT[i];
    for (int i = tid; i < NRED * NSPAN; i += 128) spanT_s[i] = spanT[i];
    for (int i = tid; i < NSPAN; i += 128) sb_s[i] = span_b[i];
    if (tid < 16) beta_s[tid] = beta[tid];

    // stage x tile with halo (zero pad OOB)
    const int NF4 = TS * TS * XC / 4;  // 3136
    for (int i = tid; i < NF4; i += 128) {
        int q = i & 15;
        int p = i >> 4;
        int yy = y0 + p / TS, xx = x0 + p % TS;
        float4 v = make_float4(0.f, 0.f, 0.f, 0.f);
        if (yy >= 0 && yy < XH && xx >= 0 && xx < XW)
            v = *(const float4*)&xin[(yy * XW + xx) * XC + q * 4];
        *(float4*)&xs[p * XC + q * 4] = v;
    }
    __syncthreads();

    for (int pp = warp; pp < TILE * TILE; pp += 4) {
        int py = pp / TILE, px = pp % TILE;
        int gy = by * TILE + py, gx = bx * TILE + px;
        if (gy >= XH || gx >= XW) continue;   // warp-uniform

        const float* xp = &xs[((py + 3) * TS + (px + 3)) * XC];

        // ---- t = relu(gamma*(red_w @ x) + beta), split 2 halves across lanes
        int half = lane >> 4, r = lane & 15;
        const float* xh  = xp + half * 32;
        const float* rwh = redT_s + half * 32 * NRED + r;
        float a0 = 0.f, a1 = 0.f;
#pragma unroll
        for (int c = 0; c < 32; c += 2) {
            a0 = fmaf(rwh[c * NRED], xh[c], a0);
            a1 = fmaf(rwh[(c + 1) * NRED], xh[c + 1], a1);
        }
        float acc = a0 + a1;
        acc += __shfl_down_sync(0xffffffffu, acc, 16);
        if (lane < 16) t_s[warp * 16 + r] = fmaxf(acc + beta_s[r], 0.f);
        __syncwarp();

        // ---- ker[196] = span_w @ t + span_b
        const float* tw = &t_s[warp * 16];
#pragma unroll
        for (int i = 0; i < 7; i++) {
            int j = lane + 32 * i;
            if (j < NSPAN) {
                float k0 = sb_s[j], k1 = 0.f;
#pragma unroll
                for (int r2 = 0; r2 < 16; r2 += 2) {
                    k0 = fmaf(spanT_s[r2 * NSPAN + j], tw[r2], k0);
                    k1 = fmaf(spanT_s[(r2 + 1) * NSPAN + j], tw[r2 + 1], k1);
                }
                ker_s[warp * 200 + j] = k0 + k1;
            }
        }
        __syncwarp();

        // ---- apply: out[c] = sum_k ker[g(c),k] * x[c, neighborhood]
        int c0 = lane * 2;
        const float* kg = &ker_s[warp * 200 + (c0 >> 4) * 49];
        float o0a = 0.f, o1a = 0.f, o0b = 0.f, o1b = 0.f;
#pragma unroll
        for (int dy = 0; dy < 7; dy++) {
            const float* row = &xs[((py + dy) * TS + px) * XC + c0];
#pragma unroll
            for (int dx = 0; dx < 7; dx++) {
                float kw = kg[dy * 7 + dx];
                float2 xv = *(const float2*)&row[dx * XC];
                if ((dx & 1) == 0) { o0a = fmaf(kw, xv.x, o0a); o1a = fmaf(kw, xv.y, o1a); }
                else               { o0b = fmaf(kw, xv.x, o0b); o1b = fmaf(kw, xv.y, o1b); }
            }
        }
        float2 ov = make_float2(fmaxf(o0a + o0b, 0.f), fmaxf(o1a + o1b, 0.f));
        *(float2*)&xout[(gy * XW + gx) * XC + c0] = ov;
        __syncwarp();
    }
}

// ---------------- conv_out (64->12, 3x3, pad 0) fused with PixelShuffle(2) ----------------
__global__ void conv_out_kernel(const float* __restrict__ x,
                                const float* __restrict__ w,
                                const float* __restrict__ b,
                                float* __restrict__ out) {
    __shared__ float wS[9 * 12 * 64];   // [tap][oc][c]
    __shared__ float bS[12];
    int tid = threadIdx.x;
    for (int i = tid; i < 9 * 12 * 64; i += blockDim.x) {
        int c = i & 63;
        int rest = i >> 6;
        int oc = rest % 12, tap = rest / 12;
        wS[(tap * 12 + oc) * 64 + c] = w[(oc * 64 + c) * 9 + tap];
    }
    if (tid < 12) bS[tid] = b[tid];
    __syncthreads();

    int lane = tid & 31, warp = tid >> 5;
    int c0 = lane * 2;
    int nwarps = gridDim.x * (blockDim.x >> 5);
    for (int pix = blockIdx.x * (blockDim.x >> 5) + warp; pix < 128 * 128; pix += nwarps) {
        int y = pix >> 7, xc = pix & 127;
        float o[12];
#pragma unroll
        for (int oc = 0; oc < 12; oc++) o[oc] = 0.f;
#pragma unroll
        for (int ky = 0; ky < 3; ky++)
#pragma unroll
            for (int kx = 0; kx < 3; kx++) {
                int tap = ky * 3 + kx;
                float2 xv = *(const float2*)&x[((y + ky) * XW + (xc + kx)) * XC + c0];
#pragma unroll
                for (int oc = 0; oc < 12; oc++) {
                    float2 wv = *(const float2*)&wS[(tap * 12 + oc) * 64 + c0];
                    o[oc] = fmaf(wv.x, xv.x, o[oc]);
                    o[oc] = fmaf(wv.y, xv.y, o[oc]);
                }
            }
#pragma unroll
        for (int oc = 0; oc < 12; oc++) {
#pragma unroll
            for (int s = 16; s > 0; s >>= 1)
                o[oc] += __shfl_xor_sync(0xffffffffu, o[oc], s);
        }
        if (lane == 0) {
#pragma unroll
            for (int oc = 0; oc < 12; oc++) {
                int co = oc >> 2, rem = oc & 3;
                int dy = rem >> 1, dx = rem & 1;
                out[(co * 256 + (2 * y + dy)) * 256 + (2 * xc + dx)] = o[oc] + bS[oc];
            }
        }
    }
}

// ---------------- launch ----------------
extern "C" void kernel_launch(void* const* d_in, const int* in_sizes, int n_in,
                              void* d_out, int out_size) {
    const float* input      = (const float*)d_in[0];
    const float* conv_in_w  = (const float*)d_in[1];
    const float* conv_in_b  = (const float*)d_in[2];
    const float* red_w      = (const float*)d_in[3];
    const float* bn_gamma   = (const float*)d_in[4];
    const float* bn_beta    = (const float*)d_in[5];
    const float* span_w     = (const float*)d_in[6];
    const float* span_b     = (const float*)d_in[7];
    const float* conv_out_w = (const float*)d_in[8];
    const float* conv_out_b = (const float*)d_in[9];
    float* out = (float*)d_out;

    float *bufA, *bufB, *redT, *spanT;
    cudaGetSymbolAddress((void**)&bufA, g_bufA);
    cudaGetSymbolAddress((void**)&bufB, g_bufB);
    cudaGetSymbolAddress((void**)&redT, g_redT);
    cudaGetSymbolAddress((void**)&spanT, g_spanT);

    const int SMEM_INV = (TS * TS * XC + XC * NRED + NRED * NSPAN + NSPAN + 16 + 64 + 4 * 200) * 4;
    cudaFuncSetAttribute(involution_kernel, cudaFuncAttributeMaxDynamicSharedMemorySize, SMEM_INV);

    // 1. prep transposed/folded weights
    int prep_n = NLAYERS * XC * NRED + NLAYERS * NRED * NSPAN;
    prep_kernel<<<(prep_n + 255) / 256, 256>>>(red_w, bn_gamma, span_w);

    // 2. conv_in -> bufA (NHWC)
    conv_in_kernel<<<(XH * XW * XC + 255) / 256, 256>>>(input, conv_in_w, conv_in_b, bufA);

    // 3. six involution+relu layers, ping-pong A<->B (ends in A)
    for (int l = 0; l < NLAYERS; l++) {
        const float* src = (l & 1) ? bufB : bufA;
        float* dst       = (l & 1) ? bufA : bufB;
        involution_kernel<<<NTB * NTB, 128, SMEM_INV>>>(
            src, dst,
            redT + l * XC * NRED,
            spanT + l * NRED * NSPAN,
            bn_beta + l * NRED,
            span_b + l * NSPAN);
    }

    // 4. conv_out + pixel shuffle
    conv_out_kernel<<<512, 256>>>(bufA, conv_out_w, conv_out_b, out);
}

// round 2
// speedup vs baseline: 1.0924x; 1.0924x over previous
#include <cuda_runtime.h>

#define XH 130
#define XW 130
#define XC 64
#define NPIX (XH * XW)          // 16900
#define NRED 16
#define NSPAN 196
#define NLAYERS 6
#define TILE 8
#define TS 14
#define NTB 17

#define NPAIR_ALLOC 8464        // ceil(16900/2 /16)*16 = 529*16

// ---------------- scratch ----------------
__device__ float g_bufA[NPIX * XC];
__device__ float g_bufB[NPIX * XC];
__device__ float g_redT[NLAYERS][16 * 16 * 4];        // [q][r] float4 (gamma-folded)
__device__ float g_t2[NPAIR_ALLOC * 32];              // [pair][r*2+sub]
__device__ float g_ker[NPIX * NSPAN];                 // [p][196]

// ---------------- f32x2 helpers ----------------
__device__ __forceinline__ unsigned long long dup2(float k) {
    unsigned long long r;
    asm("mov.b64 %0, {%1, %1};" : "=l"(r) : "f"(k));
    return r;
}
__device__ __forceinline__ unsigned long long pack2(float x, float y) {
    unsigned long long r;
    asm("mov.b64 %0, {%1, %2};" : "=l"(r) : "f"(x), "f"(y));
    return r;
}
__device__ __forceinline__ unsigned long long fma2(unsigned long long a,
                                                   unsigned long long b,
                                                   unsigned long long c) {
    unsigned long long d;
    asm("fma.rn.f32x2 %0, %1, %2, %3;" : "=l"(d) : "l"(a), "l"(b), "l"(c));
    return d;
}
__device__ __forceinline__ float2 unpack2(unsigned long long v) {
    float2 r;
    asm("mov.b64 {%0, %1}, %2;" : "=f"(r.x), "=f"(r.y) : "l"(v));
    return r;
}

// ---------------- prep: gamma-fold red_w into [q][r] float4 layout ----------------
__global__ void prep_kernel(const float* __restrict__ red_w,
                            const float* __restrict__ gamma) {
    int idx = blockIdx.x * blockDim.x + threadIdx.x;
    if (idx >= NLAYERS * 16 * 64) return;
    int l = idx / 1024, rem = idx % 1024;
    int r = rem / 64, c = rem % 64;
    g_redT[l][((c >> 2) * 16 + r) * 4 + (c & 3)] =
        gamma[l * 16 + r] * red_w[(l * 16 + r) * 64 + c];
}

// ---------------- conv_in: 3->64, 3x3, pad 2 ; NCHW -> NHWC ----------------
__global__ void conv_in_kernel(const float* __restrict__ in,
                               const float* __restrict__ w,
                               const float* __restrict__ b,
                               float* __restrict__ out) {
    __shared__ float ws[27 * 64];
    int tid = threadIdx.x;
    for (int i = tid; i < 27 * 64; i += blockDim.x) {
        int t = i >> 6, c = i & 63;
        ws[t * 64 + c] = w[c * 27 + t];
    }
    __syncthreads();
    int idx = blockIdx.x * blockDim.x + tid;
    if (idx >= NPIX * XC) return;
    int c = idx & 63;
    int p = idx >> 6;
    int y = p / XW, x = p % XW;
    float acc = b[c];
#pragma unroll
    for (int i = 0; i < 3; i++)
#pragma unroll
        for (int ky = 0; ky < 3; ky++) {
            int yy = y + ky - 2;
            if (yy < 0 || yy >= 128) continue;
#pragma unroll
            for (int kx = 0; kx < 3; kx++) {
                int xx = x + kx - 2;
                if (xx < 0 || xx >= 128) continue;
                acc = fmaf(ws[(i * 9 + ky * 3 + kx) * 64 + c],
                           in[(i * 128 + yy) * 128 + xx], acc);
            }
        }
    out[p * 64 + c] = acc;
}

// ---------------- t kernel: t[p][16] = relu(redT @ x[p] + beta), pair-interleaved ----------------
__global__ void __launch_bounds__(256)
t_kernel(const float* __restrict__ xin, const float* __restrict__ redT4,
         const float* __restrict__ beta, float* __restrict__ t2) {
    __shared__ float xs[16 * 64];
    __shared__ float rw[16 * 16 * 4];
    __shared__ float beta_s[16];
    int tid = threadIdx.x;
    int p0 = blockIdx.x * 16;

    // stage x (16 pixels), redT, beta
    {
        int gi = p0 * 64 + tid * 4;
        float4 v = make_float4(0.f, 0.f, 0.f, 0.f);
        if (gi < NPIX * 64) v = *(const float4*)&xin[gi];
        *(float4*)&xs[tid * 4] = v;
        *(float4*)&rw[tid * 4] = *(const float4*)&redT4[tid * 4];
        if (tid < 16) beta_s[tid] = beta[tid];
    }
    __syncthreads();

    int lane = tid & 31, w = tid >> 5;
    int h = lane >> 4, r = lane & 15;
    int px_loc = w * 2 + h;
    int p = p0 + px_loc;

    float acc = 0.f;
    const float* xp = &xs[px_loc * 64];
#pragma unroll
    for (int q = 0; q < 16; q++) {
        float4 wv = *(const float4*)&rw[(q * 16 + r) * 4];
        float4 xv = *(const float4*)&xp[q * 4];
        acc = fmaf(wv.x, xv.x, acc);
        acc = fmaf(wv.y, xv.y, acc);
        acc = fmaf(wv.z, xv.z, acc);
        acc = fmaf(wv.w, xv.w, acc);
    }
    float tv = fmaxf(acc + beta_s[r], 0.f);
    if (p < NPIX) t2[(p0 / 2 + w) * 32 + r * 2 + h] = tv;
}

// ---------------- ker GEMM: ker[p][j] = span_w[j][:] @ t[p][:] + span_b[j] ----------------
__global__ void __launch_bounds__(224)
kerg_kernel(const float* __restrict__ t2, const float* __restrict__ span_w,
            const float* __restrict__ span_b, float* __restrict__ ker) {
    __shared__ float ts[16 * 32];
    int tid = threadIdx.x, lane = tid & 31, w = tid >> 5;
    int j = w * 32 + lane;
    bool jok = (j < NSPAN);

    // weights in registers (duplicated for f32x2)
    unsigned long long wd[16];
    float sb = 0.f;
    {
        float wr[16];
#pragma unroll
        for (int q = 0; q < 4; q++) {
            float4 v = make_float4(0.f, 0.f, 0.f, 0.f);
            if (jok) v = *(const float4*)&span_w[j * 16 + q * 4];
            wr[q * 4 + 0] = v.x; wr[q * 4 + 1] = v.y;
            wr[q * 4 + 2] = v.z; wr[q * 4 + 3] = v.w;
        }
        if (jok) sb = span_b[j];
#pragma unroll
        for (int r = 0; r < 16; r++) wd[r] = dup2(wr[r]);
    }

    int pair0 = blockIdx.x * 16;
    for (int i = tid; i < 512; i += 224) ts[i] = t2[pair0 * 32 + i];
    __syncthreads();

#pragma unroll
    for (int pp = 0; pp < 16; pp += 4) {
        unsigned long long a[4];
#pragma unroll
        for (int pq = 0; pq < 4; pq++) a[pq] = 0ull;
        const float* tb = &ts[pp * 32];
#pragma unroll
        for (int r = 0; r < 16; r += 2) {
#pragma unroll
            for (int pq = 0; pq < 4; pq++) {
                float4 tv = *(const float4*)&tb[pq * 32 + r * 2];
                a[pq] = fma2(wd[r],     pack2(tv.x, tv.y), a[pq]);
                a[pq] = fma2(wd[r + 1], pack2(tv.z, tv.w), a[pq]);
            }
        }
        if (jok) {
#pragma unroll
            for (int pq = 0; pq < 4; pq++) {
                float2 k = unpack2(a[pq]);
                int p = (pair0 + pp + pq) * 2;
                if (p < NPIX)     ker[p * NSPAN + j]       = k.x + sb;
                if (p + 1 < NPIX) ker[(p + 1) * NSPAN + j] = k.y + sb;
            }
        }
    }
}

// ---------------- apply: out[p][c] = relu(sum_tap ker[p][g][tap] * x[nbr][c]) ----------------
__global__ void __launch_bounds__(512, 2)
apply_kernel(const float* __restrict__ xin, const float* __restrict__ kerg,
             float* __restrict__ xout) {
    extern __shared__ float sm[];
    float* xs   = sm;                      // 14*14*64 = 12544
    float* sker = xs + TS * TS * XC;       // 64*4*7*8 = 14336 (padded rows of 8)
    int* offs   = (int*)(sker + 64 * 4 * 7 * 8);  // 196

    int tid = threadIdx.x, lane = tid & 31, w = tid >> 5;
    int by = blockIdx.x / NTB, bx = blockIdx.x % NTB;
    int y0 = by * TILE - 3, x0 = bx * TILE - 3;

    // offset table for ker repacking
    for (int i = tid; i < NSPAN; i += 512) {
        int g = i / 49, q = i % 49;
        offs[i] = g * 56 + (q / 7) * 8 + (q % 7);
    }
    // stage x tile (zero-padded halo)
    for (int i = tid; i < TS * TS * 16; i += 512) {
        int q = i & 15, p = i >> 4;
        int yy = y0 + p / TS, xx = x0 + p % TS;
        float4 v = make_float4(0.f, 0.f, 0.f, 0.f);
        if (yy >= 0 && yy < XH && xx >= 0 && xx < XW)
            v = *(const float4*)&xin[(yy * XW + xx) * XC + q * 4];
        *(float4*)&xs[p * XC + q * 4] = v;
    }
    __syncthreads();   // offs ready before repack uses it
    // stage ker (padded layout: [pl][g][dy][8])
    for (int pl = w; pl < 64; pl += 16) {
        int gy = by * TILE + (pl >> 3), gx = bx * TILE + (pl & 7);
        bool ok = (gy < XH && gx < XW);
        int pbase = (gy * XW + gx) * NSPAN;
        for (int r = lane; r < NSPAN; r += 32) {
            float v = ok ? kerg[pbase + r] : 0.f;
            sker[pl * 224 + offs[r]] = v;
        }
    }
    __syncthreads();

    // compute: warp = column px, 4 vertical pixels starting at py0
    int px = w & 7, py0 = (w >> 3) * 4;
    int g = lane >> 3;
    int c0 = lane * 2;

    unsigned long long acc[4] = {0ull, 0ull, 0ull, 0ull};
#pragma unroll
    for (int dya = 0; dya < 10; dya++) {
        unsigned long long xr[7];
        const float* row = &xs[((py0 + dya) * TS + px) * XC + c0];
#pragma unroll
        for (int dx = 0; dx < 7; dx++)
            xr[dx] = *(const unsigned long long*)&row[dx * XC];
#pragma unroll
        for (int pr = 0; pr < 4; pr++) {
            int dy = dya - pr;
            if (dy < 0 || dy > 6) continue;
            int pl = (py0 + pr) * 8 + px;
            const float4* kp = (const float4*)&sker[(pl * 4 + g) * 56 + dy * 8];
            float4 ka = kp[0], kb = kp[1];
            acc[pr] = fma2(dup2(ka.x), xr[0], acc[pr]);
            acc[pr] = fma2(dup2(ka.y), xr[1], acc[pr]);
            acc[pr] = fma2(dup2(ka.z), xr[2], acc[pr]);
            acc[pr] = fma2(dup2(ka.w), xr[3], acc[pr]);
            acc[pr] = fma2(dup2(kb.x), xr[4], acc[pr]);
            acc[pr] = fma2(dup2(kb.y), xr[5], acc[pr]);
            acc[pr] = fma2(dup2(kb.z), xr[6], acc[pr]);
        }
    }

    int gx = bx * TILE + px;
    if (gx < XW) {
#pragma unroll
        for (int pr = 0; pr < 4; pr++) {
            int gy = by * TILE + py0 + pr;
            if (gy < XH) {
                float2 o = unpack2(acc[pr]);
                o.x = fmaxf(o.x, 0.f);
                o.y = fmaxf(o.y, 0.f);
                *(float2*)&xout[(gy * XW + gx) * XC + c0] = o;
            }
        }
    }
}

// ---------------- conv_out (64->12, 3x3) + PixelShuffle(2) ----------------
__global__ void conv_out_kernel(const float* __restrict__ x,
                                const float* __restrict__ w,
                                const float* __restrict__ b,
                                float* __restrict__ out) {
    __shared__ float wS[9 * 12 * 64];
    __shared__ float bS[12];
    int tid = threadIdx.x;
    for (int i = tid; i < 9 * 12 * 64; i += blockDim.x) {
        int c = i & 63;
        int rest = i >> 6;
        int oc = rest % 12, tap = rest / 12;
        wS[(tap * 12 + oc) * 64 + c] = w[(oc * 64 + c) * 9 + tap];
    }
    if (tid < 12) bS[tid] = b[tid];
    __syncthreads();

    int lane = tid & 31, warp = tid >> 5;
    int c0 = lane * 2;
    int nwarps = gridDim.x * (blockDim.x >> 5);
    for (int pix = blockIdx.x * (blockDim.x >> 5) + warp; pix < 128 * 128; pix += nwarps) {
        int y = pix >> 7, xc = pix & 127;
        float o[12];
#pragma unroll
        for (int oc = 0; oc < 12; oc++) o[oc] = 0.f;
#pragma unroll
        for (int ky = 0; ky < 3; ky++)
#pragma unroll
            for (int kx = 0; kx < 3; kx++) {
                int tap = ky * 3 + kx;
                float2 xv = *(const float2*)&x[((y + ky) * XW + (xc + kx)) * XC + c0];
#pragma unroll
                for (int oc = 0; oc < 12; oc++) {
                    float2 wv = *(const float2*)&wS[(tap * 12 + oc) * 64 + c0];
                    o[oc] = fmaf(wv.x, xv.x, o[oc]);
                    o[oc] = fmaf(wv.y, xv.y, o[oc]);
                }
            }
#pragma unroll
        for (int oc = 0; oc < 12; oc++) {
#pragma unroll
            for (int s = 16; s > 0; s >>= 1)
                o[oc] += __shfl_xor_sync(0xffffffffu, o[oc], s);
        }
        if (lane == 0) {
#pragma unroll
            for (int oc = 0; oc < 12; oc++) {
                int co = oc >> 2, rem = oc & 3;
                int dy = rem >> 1, dx = rem & 1;
                out[(co * 256 + (2 * y + dy)) * 256 + (2 * xc + dx)] = o[oc] + bS[oc];
            }
        }
    }
}

// ---------------- launch ----------------
extern "C" void kernel_launch(void* const* d_in, const int* in_sizes, int n_in,
                              void* d_out, int out_size) {
    const float* input      = (const float*)d_in[0];
    const float* conv_in_w  = (const float*)d_in[1];
    const float* conv_in_b  = (const float*)d_in[2];
    const float* red_w      = (const float*)d_in[3];
    const float* bn_gamma   = (const float*)d_in[4];
    const float* bn_beta    = (const float*)d_in[5];
    const float* span_w     = (const float*)d_in[6];
    const float* span_b     = (const float*)d_in[7];
    const float* conv_out_w = (const float*)d_in[8];
    const float* conv_out_b = (const float*)d_in[9];
    float* out = (float*)d_out;

    float *bufA, *bufB, *redT, *t2, *ker;
    cudaGetSymbolAddress((void**)&bufA, g_bufA);
    cudaGetSymbolAddress((void**)&bufB, g_bufB);
    cudaGetSymbolAddress((void**)&redT, g_redT);
    cudaGetSymbolAddress((void**)&t2, g_t2);
    cudaGetSymbolAddress((void**)&ker, g_ker);

    const int SMEM_APPLY = (TS * TS * XC + 64 * 4 * 7 * 8) * 4 + NSPAN * 4;
    static int attr_set = 0;
    cudaFuncSetAttribute(apply_kernel, cudaFuncAttributeMaxDynamicSharedMemorySize, SMEM_APPLY);
    (void)attr_set;

    prep_kernel<<<(NLAYERS * 1024 + 255) / 256, 256>>>(red_w, bn_gamma);
    conv_in_kernel<<<(NPIX * XC + 255) / 256, 256>>>(input, conv_in_w, conv_in_b, bufA);

    for (int l = 0; l < NLAYERS; l++) {
        const float* src = (l & 1) ? bufB : bufA;
        float* dst       = (l & 1) ? bufA : bufB;
        t_kernel<<<(NPIX + 15) / 16, 256>>>(src, redT + l * 1024, bn_beta + l * 16, t2);
        kerg_kernel<<<NPAIR_ALLOC / 16, 224>>>(t2, span_w + l * NSPAN * NRED,
                                               span_b + l * NSPAN, ker);
        apply_kernel<<<NTB * NTB, 512, SMEM_APPLY>>>(src, ker, dst);
    }

    conv_out_kernel<<<512, 256>>>(bufA, conv_out_w, conv_out_b, out);
}

// round 3
// speedup vs baseline: 1.5104x; 1.3826x over previous
#include <cuda_runtime.h>

#define XH 130
#define XW 130
#define XC 64
#define NPIX (XH * XW)
#define NRED 16
#define NSPAN 196
#define NLAYERS 6
#define TILE 8
#define TS 14
#define NTB 17

// ---------------- scratch ----------------
__device__ float g_bufA[NPIX * XC];
__device__ float g_bufB[NPIX * XC];
__device__ float g_redT[NLAYERS][16 * 16 * 4];   // [q][r] float4 (gamma-folded)

// ---------------- f32x2 helpers ----------------
__device__ __forceinline__ unsigned long long dup2(float k) {
    unsigned long long r;
    asm("mov.b64 %0, {%1, %1};" : "=l"(r) : "f"(k));
    return r;
}
__device__ __forceinline__ unsigned long long fma2(unsigned long long a,
                                                   unsigned long long b,
                                                   unsigned long long c) {
    unsigned long long d;
    asm("fma.rn.f32x2 %0, %1, %2, %3;" : "=l"(d) : "l"(a), "l"(b), "l"(c));
    return d;
}
__device__ __forceinline__ float2 unpack2(unsigned long long v) {
    float2 r;
    asm("mov.b64 {%0, %1}, %2;" : "=f"(r.x), "=f"(r.y) : "l"(v));
    return r;
}

// ---------------- prep: gamma-fold red_w into [q][r] float4 layout ----------------
__global__ void prep_kernel(const float* __restrict__ red_w,
                            const float* __restrict__ gamma) {
    int idx = blockIdx.x * blockDim.x + threadIdx.x;
    if (idx >= NLAYERS * 16 * 64) return;
    int l = idx / 1024, rem = idx % 1024;
    int r = rem / 64, c = rem % 64;
    g_redT[l][((c >> 2) * 16 + r) * 4 + (c & 3)] =
        gamma[l * 16 + r] * red_w[(l * 16 + r) * 64 + c];
}

// ---------------- conv_in: 3->64, 3x3, pad 2 ; NCHW -> NHWC ----------------
__global__ void conv_in_kernel(const float* __restrict__ in,
                               const float* __restrict__ w,
                               const float* __restrict__ b,
                               float* __restrict__ out) {
    __shared__ float ws[27 * 64];
    int tid = threadIdx.x;
    for (int i = tid; i < 27 * 64; i += blockDim.x) {
        int t = i >> 6, c = i & 63;
        ws[t * 64 + c] = w[c * 27 + t];
    }
    __syncthreads();
    int idx = blockIdx.x * blockDim.x + tid;
    if (idx >= NPIX * XC) return;
    int c = idx & 63;
    int p = idx >> 6;
    int y = p / XW, x = p % XW;
    float acc = b[c];
#pragma unroll
    for (int i = 0; i < 3; i++)
#pragma unroll
        for (int ky = 0; ky < 3; ky++) {
            int yy = y + ky - 2;
            if (yy < 0 || yy >= 128) continue;
#pragma unroll
            for (int kx = 0; kx < 3; kx++) {
                int xx = x + kx - 2;
                if (xx < 0 || xx >= 128) continue;
                acc = fmaf(ws[(i * 9 + ky * 3 + kx) * 64 + c],
                           in[(i * 128 + yy) * 128 + xx], acc);
            }
        }
    out[p * 64 + c] = acc;
}

// ---------------- fused involution layer ----------------
// smem: xs[12544] | sker[14336] (aliased by redT[1024] during t phase) |
//       t2[1024] | beta[16]
#define SM_XS   0
#define SM_SKER (TS * TS * XC)                // 12544
#define SM_T2   (SM_SKER + 64 * 224)          // 26880
#define SM_BETA (SM_T2 + 1024)                // 27904
#define SM_TOT  (SM_BETA + 16)                // 27920 floats

__global__ void __launch_bounds__(512, 2)
inv_kernel(const float* __restrict__ xin, float* __restrict__ xout,
           const float* __restrict__ redT4, const float* __restrict__ beta,
           const float* __restrict__ span_w, const float* __restrict__ span_b) {
    extern __shared__ float sm[];
    float* xs     = sm + SM_XS;
    float* sker   = sm + SM_SKER;
    float* redT_s = sker;           // alias: redT used before sker is written
    float* t2_s   = sm + SM_T2;
    float* beta_s = sm + SM_BETA;

    int tid = threadIdx.x, lane = tid & 31, w = tid >> 5;
    int by = blockIdx.x / NTB, bx = blockIdx.x % NTB;
    int y0 = by * TILE - 3, x0 = bx * TILE - 3;

    // ---- span weights into registers (fixed lane->j mapping) ----
    int jb   = (w < 7) ? w : ((w < 14) ? w - 7 : w - 14);
    int sub  = (w < 7) ? 0 : ((w < 14) ? 1 : 2);
    int nsub = (jb < 2) ? 3 : 2;
    int j = jb * 32 + lane;
    bool jok = (j < NSPAN);
    unsigned long long wd[16], sbd = 0ull;
    {
        float wr[16];
#pragma unroll
        for (int q = 0; q < 4; q++) {
            float4 v = make_float4(0.f, 0.f, 0.f, 0.f);
            if (jok) v = *(const float4*)&span_w[j * 16 + q * 4];
            wr[q * 4] = v.x; wr[q * 4 + 1] = v.y; wr[q * 4 + 2] = v.z; wr[q * 4 + 3] = v.w;
        }
#pragma unroll
        for (int r = 0; r < 16; r++) wd[r] = dup2(wr[r]);
        if (jok) sbd = dup2(span_b[j]);
    }
    // target offset inside a pixel's 224-float ker row
    int goff;
    {
        int g = j / 49, q = j % 49;
        goff = g * 56 + (q / 7) * 8 + (q % 7);
    }

    // ---- stage x tile (zero-padded halo), redT, beta ----
    for (int i = tid; i < TS * TS * 16; i += 512) {
        int q = i & 15, p = i >> 4;
        int yy = y0 + p / TS, xx = x0 + p % TS;
        float4 v = make_float4(0.f, 0.f, 0.f, 0.f);
        if (yy >= 0 && yy < XH && xx >= 0 && xx < XW)
            v = *(const float4*)&xin[(yy * XW + xx) * XC + q * 4];
        *(float4*)&xs[p * XC + q * 4] = v;
    }
    if (tid < 256) *(float4*)&redT_s[tid * 4] = *(const float4*)&redT4[tid * 4];
    if (tid < 16) beta_s[tid] = beta[tid];
    __syncthreads();

    // ---- t phase: t[p][r] = relu(redT @ x[p] + beta), pair-interleaved ----
    {
        int p = tid >> 3;                 // local pixel 0..63
        int rb = (tid & 7) * 2;           // two r values
        int py = p >> 3, px = p & 7;
        const float* xp = &xs[((py + 3) * TS + (px + 3)) * XC];
        float a0 = 0.f, a1 = 0.f;
#pragma unroll
        for (int q = 0; q < 16; q++) {
            float4 xv = *(const float4*)&xp[q * 4];
            float4 w0 = *(const float4*)&redT_s[(q * 16 + rb) * 4];
            float4 w1 = *(const float4*)&redT_s[(q * 16 + rb + 1) * 4];
            a0 = fmaf(w0.x, xv.x, a0); a0 = fmaf(w0.y, xv.y, a0);
            a0 = fmaf(w0.z, xv.z, a0); a0 = fmaf(w0.w, xv.w, a0);
            a1 = fmaf(w1.x, xv.x, a1); a1 = fmaf(w1.y, xv.y, a1);
            a1 = fmaf(w1.z, xv.z, a1); a1 = fmaf(w1.w, xv.w, a1);
        }
        int base = (p >> 1) * 32 + (p & 1);
        t2_s[base + rb * 2]       = fmaxf(a0 + beta_s[rb], 0.f);
        t2_s[base + (rb + 1) * 2] = fmaxf(a1 + beta_s[rb + 1], 0.f);
    }
    __syncthreads();   // t done; redT_s dead -> sker may be written

    // ---- ker phase: ker[p][j] = span_w[j] @ t[p] + span_b[j] -> sker (padded) ----
    for (int pair = sub; pair < 32; pair += nsub) {
        const unsigned long long* tp = (const unsigned long long*)&t2_s[pair * 32];
        unsigned long long acc = sbd;
#pragma unroll
        for (int r = 0; r < 16; r++) acc = fma2(wd[r], tp[r], acc);
        if (jok) {
            float2 k = unpack2(acc);
            sker[(pair * 2) * 224 + goff]     = k.x;
            sker[(pair * 2 + 1) * 224 + goff] = k.y;
        }
    }
    __syncthreads();

    // ---- apply phase: warp = column px, 4 vertical pixels ----
    {
        int px = w & 7, py0 = (w >> 3) * 4;
        int g = lane >> 3;
        int c0 = lane * 2;
        unsigned long long acc[4] = {0ull, 0ull, 0ull, 0ull};
#pragma unroll
        for (int dya = 0; dya < 10; dya++) {
            unsigned long long xr[7];
            const float* row = &xs[((py0 + dya) * TS + px) * XC + c0];
#pragma unroll
            for (int dx = 0; dx < 7; dx++)
                xr[dx] = *(const unsigned long long*)&row[dx * XC];
#pragma unroll
            for (int pr = 0; pr < 4; pr++) {
                int dy = dya - pr;
                if (dy < 0 || dy > 6) continue;
                int pl = (py0 + pr) * 8 + px;
                const float4* kp = (const float4*)&sker[(pl * 4 + g) * 56 + dy * 8];
                float4 ka = kp[0], kb = kp[1];
                acc[pr] = fma2(dup2(ka.x), xr[0], acc[pr]);
                acc[pr] = fma2(dup2(ka.y), xr[1], acc[pr]);
                acc[pr] = fma2(dup2(ka.z), xr[2], acc[pr]);
                acc[pr] = fma2(dup2(ka.w), xr[3], acc[pr]);
                acc[pr] = fma2(dup2(kb.x), xr[4], acc[pr]);
                acc[pr] = fma2(dup2(kb.y), xr[5], acc[pr]);
                acc[pr] = fma2(dup2(kb.z), xr[6], acc[pr]);
            }
        }
        int gx = bx * TILE + px;
        if (gx < XW) {
#pragma unroll
            for (int pr = 0; pr < 4; pr++) {
                int gy = by * TILE + py0 + pr;
                if (gy < XH) {
                    float2 o = unpack2(acc[pr]);
                    o.x = fmaxf(o.x, 0.f);
                    o.y = fmaxf(o.y, 0.f);
                    *(float2*)&xout[(gy * XW + gx) * XC + c0] = o;
                }
            }
        }
    }
}

// ---------------- conv_out (64->12, 3x3) + PixelShuffle(2) ----------------
__global__ void conv_out_kernel(const float* __restrict__ x,
                                const float* __restrict__ w,
                                const float* __restrict__ b,
                                float* __restrict__ out) {
    __shared__ float wS[9 * 12 * 64];
    __shared__ float bS[12];
    int tid = threadIdx.x;
    for (int i = tid; i < 9 * 12 * 64; i += blockDim.x) {
        int c = i & 63;
        int rest = i >> 6;
        int oc = rest % 12, tap = rest / 12;
        wS[(tap * 12 + oc) * 64 + c] = w[(oc * 64 + c) * 9 + tap];
    }
    if (tid < 12) bS[tid] = b[tid];
    __syncthreads();

    int lane = tid & 31, warp = tid >> 5;
    int c0 = lane * 2;
    int nwarps = gridDim.x * (blockDim.x >> 5);
    for (int pix = blockIdx.x * (blockDim.x >> 5) + warp; pix < 128 * 128; pix += nwarps) {
        int y = pix >> 7, xc = pix & 127;
        float o[12];
#pragma unroll
        for (int oc = 0; oc < 12; oc++) o[oc] = 0.f;
#pragma unroll
        for (int ky = 0; ky < 3; ky++)
#pragma unroll
            for (int kx = 0; kx < 3; kx++) {
                int tap = ky * 3 + kx;
                float2 xv = *(const float2*)&x[((y + ky) * XW + (xc + kx)) * XC + c0];
#pragma unroll
                for (int oc = 0; oc < 12; oc++) {
                    float2 wv = *(const float2*)&wS[(tap * 12 + oc) * 64 + c0];
                    o[oc] = fmaf(wv.x, xv.x, o[oc]);
                    o[oc] = fmaf(wv.y, xv.y, o[oc]);
                }
            }
#pragma unroll
        for (int oc = 0; oc < 12; oc++) {
#pragma unroll
            for (int s = 16; s > 0; s >>= 1)
                o[oc] += __shfl_xor_sync(0xffffffffu, o[oc], s);
        }
        if (lane == 0) {
#pragma unroll
            for (int oc = 0; oc < 12; oc++) {
                int co = oc >> 2, rem = oc & 3;
                int dy = rem >> 1, dx = rem & 1;
                out[(co * 256 + (2 * y + dy)) * 256 + (2 * xc + dx)] = o[oc] + bS[oc];
            }
        }
    }
}

// ---------------- launch ----------------
extern "C" void kernel_launch(void* const* d_in, const int* in_sizes, int n_in,
                              void* d_out, int out_size) {
    const float* input      = (const float*)d_in[0];
    const float* conv_in_w  = (const float*)d_in[1];
    const float* conv_in_b  = (const float*)d_in[2];
    const float* red_w      = (const float*)d_in[3];
    const float* bn_gamma   = (const float*)d_in[4];
    const float* bn_beta    = (const float*)d_in[5];
    const float* span_w     = (const float*)d_in[6];
    const float* span_b     = (const float*)d_in[7];
    const float* conv_out_w = (const float*)d_in[8];
    const float* conv_out_b = (const float*)d_in[9];
    float* out = (float*)d_out;

    float *bufA, *bufB, *redT;
    cudaGetSymbolAddress((void**)&bufA, g_bufA);
    cudaGetSymbolAddress((void**)&bufB, g_bufB);
    cudaGetSymbolAddress((void**)&redT, g_redT);

    const int SMEM_INV = SM_TOT * 4;   // 111,680 B
    cudaFuncSetAttribute(inv_kernel, cudaFuncAttributeMaxDynamicSharedMemorySize, SMEM_INV);

    prep_kernel<<<(NLAYERS * 1024 + 255) / 256, 256>>>(red_w, bn_gamma);
    conv_in_kernel<<<(NPIX * XC + 255) / 256, 256>>>(input, conv_in_w, conv_in_b, bufA);

    for (int l = 0; l < NLAYERS; l++) {
        const float* src = (l & 1) ? bufB : bufA;
        float* dst       = (l & 1) ? bufA : bufB;
        inv_kernel<<<NTB * NTB, 512, SMEM_INV>>>(
            src, dst, redT + l * 1024, bn_beta + l * 16,
            span_w + l * NSPAN * NRED, span_b + l * NSPAN);
    }

    conv_out_kernel<<<512, 256>>>(bufA, conv_out_w, conv_out_b, out);
}

// round 4
// speedup vs baseline: 1.5113x; 1.0006x over previous
#include <cuda_runtime.h>

#define XH 130
#define XW 130
#define XC 64
#define NPIX (XH * XW)
#define NRED 16
#define NSPAN 196
#define NLAYERS 6
#define TILE 8
#define TS 14
#define NTB 17

// ---------------- scratch ----------------
__device__ float g_bufA[NPIX * XC];
__device__ float g_bufB[NPIX * XC];
__device__ float g_redT[NLAYERS][16 * 16 * 4];   // [q][r] float4 (gamma-folded)

// ---------------- f32x2 helpers ----------------
__device__ __forceinline__ unsigned long long dup2(float k) {
    unsigned long long r;
    asm("mov.b64 %0, {%1, %1};" : "=l"(r) : "f"(k));
    return r;
}
__device__ __forceinline__ unsigned long long fma2(unsigned long long a,
                                                   unsigned long long b,
                                                   unsigned long long c) {
    unsigned long long d;
    asm("fma.rn.f32x2 %0, %1, %2, %3;" : "=l"(d) : "l"(a), "l"(b), "l"(c));
    return d;
}
__device__ __forceinline__ unsigned long long add2(unsigned long long a,
                                                   unsigned long long b) {
    unsigned long long d;
    asm("add.rn.f32x2 %0, %1, %2;" : "=l"(d) : "l"(a), "l"(b));
    return d;
}
__device__ __forceinline__ float2 unpack2(unsigned long long v) {
    float2 r;
    asm("mov.b64 {%0, %1}, %2;" : "=f"(r.x), "=f"(r.y) : "l"(v));
    return r;
}

// ---------------- prep: gamma-fold red_w into [q][r] float4 layout ----------------
__global__ void prep_kernel(const float* __restrict__ red_w,
                            const float* __restrict__ gamma) {
    int idx = blockIdx.x * blockDim.x + threadIdx.x;
    if (idx >= NLAYERS * 16 * 64) return;
    int l = idx / 1024, rem = idx % 1024;
    int r = rem / 64, c = rem % 64;
    g_redT[l][((c >> 2) * 16 + r) * 4 + (c & 3)] =
        gamma[l * 16 + r] * red_w[(l * 16 + r) * 64 + c];
}

// ---------------- conv_in: 3->64, 3x3, pad 2 ; NCHW -> NHWC ----------------
__global__ void conv_in_kernel(const float* __restrict__ in,
                               const float* __restrict__ w,
                               const float* __restrict__ b,
                               float* __restrict__ out) {
    __shared__ float ws[27 * 64];
    int tid = threadIdx.x;
    for (int i = tid; i < 27 * 64; i += blockDim.x) {
        int t = i >> 6, c = i & 63;
        ws[t * 64 + c] = w[c * 27 + t];
    }
    __syncthreads();
    int idx = blockIdx.x * blockDim.x + tid;
    if (idx >= NPIX * XC) return;
    int c = idx & 63;
    int p = idx >> 6;
    int y = p / XW, x = p % XW;
    float acc = b[c];
#pragma unroll
    for (int i = 0; i < 3; i++)
#pragma unroll
        for (int ky = 0; ky < 3; ky++) {
            int yy = y + ky - 2;
            if (yy < 0 || yy >= 128) continue;
#pragma unroll
            for (int kx = 0; kx < 3; kx++) {
                int xx = x + kx - 2;
                if (xx < 0 || xx >= 128) continue;
                acc = fmaf(ws[(i * 9 + ky * 3 + kx) * 64 + c],
                           in[(i * 128 + yy) * 128 + xx], acc);
            }
        }
    out[p * 64 + c] = acc;
}

// ---------------- fused involution layer ----------------
#define SM_XS   0
#define SM_SKER (TS * TS * XC)                // 12544
#define SM_T2   (SM_SKER + 64 * 224)          // 26880
#define SM_BETA (SM_T2 + 1024)                // 27904
#define SM_TOT  (SM_BETA + 16)                // 27920 floats

__global__ void __launch_bounds__(512, 2)
inv_kernel(const float* __restrict__ xin, float* __restrict__ xout,
           const float* __restrict__ redT4, const float* __restrict__ beta,
           const float* __restrict__ span_w, const float* __restrict__ span_b) {
    extern __shared__ float sm[];
    float* xs     = sm + SM_XS;
    float* sker   = sm + SM_SKER;
    float* redT_s = sker;           // alias: redT used before sker is written
    float* t2_s   = sm + SM_T2;
    float* beta_s = sm + SM_BETA;

    int tid = threadIdx.x, lane = tid & 31, w = tid >> 5;
    int by = blockIdx.x / NTB, bx = blockIdx.x % NTB;
    int y0 = by * TILE - 3, x0 = bx * TILE - 3;

    // ---- span weights into registers (fixed lane->j mapping) ----
    int jb   = (w < 7) ? w : ((w < 14) ? w - 7 : w - 14);
    int sub  = (w < 7) ? 0 : ((w < 14) ? 1 : 2);
    int nsub = (jb < 2) ? 3 : 2;
    int j = jb * 32 + lane;
    bool jok = (j < NSPAN);
    unsigned long long wd[16], sbd = 0ull;
    {
        float wr[16];
#pragma unroll
        for (int q = 0; q < 4; q++) {
            float4 v = make_float4(0.f, 0.f, 0.f, 0.f);
            if (jok) v = *(const float4*)&span_w[j * 16 + q * 4];
            wr[q * 4] = v.x; wr[q * 4 + 1] = v.y; wr[q * 4 + 2] = v.z; wr[q * 4 + 3] = v.w;
        }
#pragma unroll
        for (int r = 0; r < 16; r++) wd[r] = dup2(wr[r]);
        if (jok) sbd = dup2(span_b[j]);
    }
    int goff;
    {
        int g = j / 49, q = j % 49;
        goff = g * 56 + (q / 7) * 8 + (q % 7);
    }

    // ---- stage x tile (zero-padded halo), redT, beta ----
    for (int i = tid; i < TS * TS * 16; i += 512) {
        int q = i & 15, p = i >> 4;
        int yy = y0 + p / TS, xx = x0 + p % TS;
        float4 v = make_float4(0.f, 0.f, 0.f, 0.f);
        if (yy >= 0 && yy < XH && xx >= 0 && xx < XW)
            v = *(const float4*)&xin[(yy * XW + xx) * XC + q * 4];
        *(float4*)&xs[p * XC + q * 4] = v;
    }
    if (tid < 256) *(float4*)&redT_s[tid * 4] = *(const float4*)&redT4[tid * 4];
    if (tid < 16) beta_s[tid] = beta[tid];
    __syncthreads();

    // ---- t phase: t[p][r] = relu(redT @ x[p] + beta), pair-interleaved ----
    {
        int p = tid >> 3;                 // local pixel 0..63
        int rb = (tid & 7) * 2;           // two r values
        int py = p >> 3, px = p & 7;
        const float* xp = &xs[((py + 3) * TS + (px + 3)) * XC];
        float a0 = 0.f, a1 = 0.f;
#pragma unroll
        for (int q = 0; q < 16; q++) {
            float4 xv = *(const float4*)&xp[q * 4];
            float4 w0 = *(const float4*)&redT_s[(q * 16 + rb) * 4];
            float4 w1 = *(const float4*)&redT_s[(q * 16 + rb + 1) * 4];
            a0 = fmaf(w0.x, xv.x, a0); a0 = fmaf(w0.y, xv.y, a0);
            a0 = fmaf(w0.z, xv.z, a0); a0 = fmaf(w0.w, xv.w, a0);
            a1 = fmaf(w1.x, xv.x, a1); a1 = fmaf(w1.y, xv.y, a1);
            a1 = fmaf(w1.z, xv.z, a1); a1 = fmaf(w1.w, xv.w, a1);
        }
        int base = (p >> 1) * 32 + (p & 1);
        t2_s[base + rb * 2]       = fmaxf(a0 + beta_s[rb], 0.f);
        t2_s[base + (rb + 1) * 2] = fmaxf(a1 + beta_s[rb + 1], 0.f);
    }
    __syncthreads();   // t done; redT_s dead -> sker may be written

    // ---- ker phase: LDS.128 t loads, dual acc chains ----
    for (int pair = sub; pair < 32; pair += nsub) {
        const ulonglong2* tp2 = (const ulonglong2*)&t2_s[pair * 32];
        unsigned long long accA = sbd, accB = 0ull;
#pragma unroll
        for (int i = 0; i < 8; i++) {
            ulonglong2 tv = tp2[i];
            accA = fma2(wd[2 * i],     tv.x, accA);
            accB = fma2(wd[2 * i + 1], tv.y, accB);
        }
        unsigned long long acc = add2(accA, accB);
        if (jok) {
            float2 k = unpack2(acc);
            sker[(pair * 2) * 224 + goff]     = k.x;
            sker[(pair * 2 + 1) * 224 + goff] = k.y;
        }
    }
    __syncthreads();

    // ---- apply phase: warp = 2x2 pixel block ----
    {
        int px0 = (w & 3) * 2, py0 = (w >> 2) * 2;
        int g = lane >> 3;
        int c0 = lane * 2;
        unsigned long long acc[2][2] = {{0ull, 0ull}, {0ull, 0ull}};
#pragma unroll
        for (int dya = 0; dya < 8; dya++) {
            unsigned long long xr[8];
            const float* row = &xs[((py0 + dya) * TS + px0) * XC + c0];
#pragma unroll
            for (int dx = 0; dx < 8; dx++)
                xr[dx] = *(const unsigned long long*)&row[dx * XC];
#pragma unroll
            for (int r = 0; r < 2; r++) {
                int dy = dya - r;
                if (dy < 0 || dy > 6) continue;
#pragma unroll
                for (int c = 0; c < 2; c++) {
                    int pl = (py0 + r) * 8 + (px0 + c);
                    const float4* kp = (const float4*)&sker[(pl * 4 + g) * 56 + dy * 8];
                    float4 ka = kp[0], kb = kp[1];
                    acc[r][c] = fma2(dup2(ka.x), xr[c + 0], acc[r][c]);
                    acc[r][c] = fma2(dup2(ka.y), xr[c + 1], acc[r][c]);
                    acc[r][c] = fma2(dup2(ka.z), xr[c + 2], acc[r][c]);
                    acc[r][c] = fma2(dup2(ka.w), xr[c + 3], acc[r][c]);
                    acc[r][c] = fma2(dup2(kb.x), xr[c + 4], acc[r][c]);
                    acc[r][c] = fma2(dup2(kb.y), xr[c + 5], acc[r][c]);
                    acc[r][c] = fma2(dup2(kb.z), xr[c + 6], acc[r][c]);
                }
            }
        }
#pragma unroll
        for (int r = 0; r < 2; r++)
#pragma unroll
            for (int c = 0; c < 2; c++) {
                int gy = by * TILE + py0 + r;
                int gx = bx * TILE + px0 + c;
                if (gy < XH && gx < XW) {
                    float2 o = unpack2(acc[r][c]);
                    o.x = fmaxf(o.x, 0.f);
                    o.y = fmaxf(o.y, 0.f);
                    *(float2*)&xout[(gy * XW + gx) * XC + c0] = o;
                }
            }
    }
}

// ---------------- conv_out (64->12, 3x3) + PixelShuffle(2) ----------------
__global__ void conv_out_kernel(const float* __restrict__ x,
                                const float* __restrict__ w,
                                const float* __restrict__ b,
                                float* __restrict__ out) {
    __shared__ float wS[9 * 12 * 64];
    __shared__ float bS[12];
    int tid = threadIdx.x;
    for (int i = tid; i < 9 * 12 * 64; i += blockDim.x) {
        int c = i & 63;
        int rest = i >> 6;
        int oc = rest % 12, tap = rest / 12;
        wS[(tap * 12 + oc) * 64 + c] = w[(oc * 64 + c) * 9 + tap];
    }
    if (tid < 12) bS[tid] = b[tid];
    __syncthreads();

    int lane = tid & 31, warp = tid >> 5;
    int c0 = lane * 2;
    int nwarps = gridDim.x * (blockDim.x >> 5);
    for (int pix = blockIdx.x * (blockDim.x >> 5) + warp; pix < 128 * 128; pix += nwarps) {
        int y = pix >> 7, xc = pix & 127;
        float o[12];
#pragma unroll
        for (int oc = 0; oc < 12; oc++) o[oc] = 0.f;
#pragma unroll
        for (int ky = 0; ky < 3; ky++)
#pragma unroll
            for (int kx = 0; kx < 3; kx++) {
                int tap = ky * 3 + kx;
                float2 xv = *(const float2*)&x[((y + ky) * XW + (xc + kx)) * XC + c0];
#pragma unroll
                for (int oc = 0; oc < 12; oc++) {
                    float2 wv = *(const float2*)&wS[(tap * 12 + oc) * 64 + c0];
                    o[oc] = fmaf(wv.x, xv.x, o[oc]);
                    o[oc] = fmaf(wv.y, xv.y, o[oc]);
                }
            }
#pragma unroll
        for (int oc = 0; oc < 12; oc++) {
#pragma unroll
            for (int s = 16; s > 0; s >>= 1)
                o[oc] += __shfl_xor_sync(0xffffffffu, o[oc], s);
        }
        if (lane == 0) {
#pragma unroll
            for (int oc = 0; oc < 12; oc++) {
                int co = oc >> 2, rem = oc & 3;
                int dy = rem >> 1, dx = rem & 1;
                out[(co * 256 + (2 * y + dy)) * 256 + (2 * xc + dx)] = o[oc] + bS[oc];
            }
        }
    }
}

// ---------------- launch ----------------
extern "C" void kernel_launch(void* const* d_in, const int* in_sizes, int n_in,
                              void* d_out, int out_size) {
    const float* input      = (const float*)d_in[0];
    const float* conv_in_w  = (const float*)d_in[1];
    const float* conv_in_b  = (const float*)d_in[2];
    const float* red_w      = (const float*)d_in[3];
    const float* bn_gamma   = (const float*)d_in[4];
    const float* bn_beta    = (const float*)d_in[5];
    const float* span_w     = (const float*)d_in[6];
    const float* span_b     = (const float*)d_in[7];
    const float* conv_out_w = (const float*)d_in[8];
    const float* conv_out_b = (const float*)d_in[9];
    float* out = (float*)d_out;

    float *bufA, *bufB, *redT;
    cudaGetSymbolAddress((void**)&bufA, g_bufA);
    cudaGetSymbolAddress((void**)&bufB, g_bufB);
    cudaGetSymbolAddress((void**)&redT, g_redT);

    const int SMEM_INV = SM_TOT * 4;   // 111,680 B
    cudaFuncSetAttribute(inv_kernel, cudaFuncAttributeMaxDynamicSharedMemorySize, SMEM_INV);

    prep_kernel<<<(NLAYERS * 1024 + 255) / 256, 256>>>(red_w, bn_gamma);
    conv_in_kernel<<<(NPIX * XC + 255) / 256, 256>>>(input, conv_in_w, conv_in_b, bufA);

    for (int l = 0; l < NLAYERS; l++) {
        const float* src = (l & 1) ? bufB : bufA;
        float* dst       = (l & 1) ? bufA : bufB;
        inv_kernel<<<NTB * NTB, 512, SMEM_INV>>>(
            src, dst, redT + l * 1024, bn_beta + l * 16,
            span_w + l * NSPAN * NRED, span_b + l * NSPAN);
    }

    conv_out_kernel<<<512, 256>>>(bufA, conv_out_w, conv_out_b, out);
}